// round 1
// baseline (speedup 1.0000x reference)
#include <cuda_runtime.h>
#include <cstdint>
#include <cstddef>

#define BATCH 32
#define TT 4
#define NN 512
#define NROWS (BATCH * TT)  // 128

// Scratch: FFT results, SoA, duplicated to length 2N so (l-k)%N needs no mod.
__device__ float g_re[NROWS * 2 * NN];
__device__ float g_im[NROWS * 2 * NN];

// ---------------------------------------------------------------------------
// Kernel 1: 512-point complex FFT (Stockham autosort, radix-2), one row/block.
// Input rows are real (imag = 0). Writes duplicated SoA to g_re/g_im.
// ---------------------------------------------------------------------------
__global__ void __launch_bounds__(256) fft_kernel(const float* __restrict__ x) {
    __shared__ float2 bufA[NN];
    __shared__ float2 bufB[NN];
    const int row = blockIdx.x;
    const int tid = threadIdx.x;

    const float* xr = x + (size_t)row * NN;
    bufA[tid]       = make_float2(xr[tid], 0.0f);
    bufA[tid + 256] = make_float2(xr[tid + 256], 0.0f);
    __syncthreads();

    float2* X = bufA;
    float2* Y = bufB;
    // 9 stages: n = 512 -> 1, s = 1 -> 512.  m*s == 256 butterflies/stage.
    for (int stage = 0; stage < 9; stage++) {
        const int n = NN >> stage;
        const int m = n >> 1;
        const int s = 1 << stage;
        const int p = tid >> stage;        // tid / s
        const int q = tid & (s - 1);       // tid % s
        float sw, cw;
        __sincosf(-6.283185307179586f * (float)p / (float)n, &sw, &cw);
        const float2 a = X[q + s * p];
        const float2 b = X[q + s * (p + m)];
        const float2 sum = make_float2(a.x + b.x, a.y + b.y);
        const float2 dif = make_float2(a.x - b.x, a.y - b.y);
        Y[q + s * (2 * p)]     = sum;
        Y[q + s * (2 * p + 1)] = make_float2(dif.x * cw - dif.y * sw,
                                             dif.x * sw + dif.y * cw);
        __syncthreads();
        float2* t = X; X = Y; Y = t;
    }
    // Result is in X after the final swap.
    float* gr = g_re + (size_t)row * (2 * NN);
    float* gi = g_im + (size_t)row * (2 * NN);
    for (int i = tid; i < NN; i += 256) {
        const float2 v = X[i];
        gr[i] = v.x; gr[i + NN] = v.x;
        gi[i] = v.y; gi[i + NN] = v.y;
    }
}

// ---------------------------------------------------------------------------
// Kernel 2: bispectrum.  lane -> k, inner loop -> l (pairs, packed f32x2).
// out[b][0][k][l] = Re, out[b][1][k][l] = Im of mean_t y_k conj(y_l) y_{l-k}.
// ---------------------------------------------------------------------------
__device__ __forceinline__ unsigned long long pack2(float lo, float hi) {
    unsigned long long r;
    asm("mov.b64 %0, {%1, %2};" : "=l"(r) : "f"(lo), "f"(hi));
    return r;
}
__device__ __forceinline__ float2 unpack2(unsigned long long v) {
    float lo, hi;
    asm("mov.b64 {%0, %1}, %2;" : "=f"(lo), "=f"(hi) : "l"(v));
    return make_float2(lo, hi);
}
#define FMAX2(d, a, b, c) \
    asm("fma.rn.f32x2 %0, %1, %2, %3;" : "=l"(d) : "l"(a), "l"(b), "l"(c))
#define MULX2(d, a, b) \
    asm("mul.rn.f32x2 %0, %1, %2;" : "=l"(d) : "l"(a), "l"(b))

__global__ void __launch_bounds__(512, 2) bispec_kernel(float* __restrict__ out) {
    __shared__ float sre[TT][2 * NN];
    __shared__ float sim[TT][2 * NN];

    const int b   = blockIdx.y;
    const int l0  = blockIdx.x * 64;
    const int tid = threadIdx.x;

    {   // cooperative load of this batch's 4 rows (duplicated SoA), 32 KB
        const float* gr = g_re + (size_t)b * TT * (2 * NN);
        const float* gi = g_im + (size_t)b * TT * (2 * NN);
        float* dr = &sre[0][0];
        float* di = &sim[0][0];
        #pragma unroll
        for (int i = 0; i < TT * 2 * NN; i += 512) {
            dr[i + tid] = gr[i + tid];
            di[i + tid] = gi[i + tid];
        }
    }
    __syncthreads();

    const int k = tid;  // 512 threads == 512 k values
    unsigned long long AR[TT], AI[TT], NAR[TT];
    #pragma unroll
    for (int t = 0; t < TT; t++) {
        const float ar = sre[t][k];
        const float ai = sim[t][k];
        AR[t]  = pack2(ar, ar);
        AI[t]  = pack2(ai, ai);
        NAR[t] = pack2(-ar, -ar);
    }

    float* outr = out + ((size_t)(b * 2 + 0) * NN + k) * NN;
    float* outi = out + ((size_t)(b * 2 + 1) * NN + k) * NN;
    const int cm0 = NN - k;  // + l  ->  index of y[(l-k) mod N] in dup array

    for (int j = 0; j < 16; j++) {
        float2 vr[2], vi[2];
        #pragma unroll
        for (int h = 0; h < 2; h++) {
            const int l = l0 + j * 4 + h * 2;
            const int m = cm0 + l;            // in [1, 1023]
            unsigned long long arp = 0ull, arm = 0ull, ai1 = 0ull, ai2 = 0ull;
            #pragma unroll
            for (int t = 0; t < TT; t++) {
                // y_l pair: broadcast (all lanes same address), aligned (l even)
                const unsigned long long BLre =
                    *(const unsigned long long*)&sre[t][l];
                const unsigned long long BLim =
                    *(const unsigned long long*)&sim[t][l];
                // y_{l-k} pair: per-lane consecutive, possibly odd -> scalar lds
                const unsigned long long CMre = pack2(sre[t][m], sre[t][m + 1]);
                const unsigned long long CMim = pack2(sim[t][m], sim[t][m + 1]);

                unsigned long long t1, t2, pr, pi;
                // p = y_k * conj(y_l)
                MULX2(t1, AI[t], BLim);
                FMAX2(pr, AR[t], BLre, t1);   // ar*blr + ai*bli
                MULX2(t2, NAR[t], BLim);
                FMAX2(pi, AI[t], BLre, t2);   // ai*blr - ar*bli
                // acc += p * y_m   (real = rp - rm, imag = i1 + i2)
                FMAX2(arp, pr, CMre, arp);
                FMAX2(arm, pi, CMim, arm);
                FMAX2(ai1, pr, CMim, ai1);
                FMAX2(ai2, pi, CMre, ai2);
            }
            const float2 rp = unpack2(arp), rm = unpack2(arm);
            const float2 x1 = unpack2(ai1), x2 = unpack2(ai2);
            vr[h] = make_float2((rp.x - rm.x) * 0.25f, (rp.y - rm.y) * 0.25f);
            vi[h] = make_float2((x1.x + x2.x) * 0.25f, (x1.y + x2.y) * 0.25f);
        }
        const int l = l0 + j * 4;
        *(float4*)(outr + l) = make_float4(vr[0].x, vr[0].y, vr[1].x, vr[1].y);
        *(float4*)(outi + l) = make_float4(vi[0].x, vi[0].y, vi[1].x, vi[1].y);
    }
}

// ---------------------------------------------------------------------------
extern "C" void kernel_launch(void* const* d_in, const int* in_sizes, int n_in,
                              void* d_out, int out_size) {
    const float* target = (const float*)d_in[0];
    float* out = (float*)d_out;

    fft_kernel<<<NROWS, 256>>>(target);

    dim3 grid(NN / 64, BATCH);   // 8 x 32 = 256 blocks
    bispec_kernel<<<grid, 512>>>(out);

    // Second tuple element: passthrough of target, if the harness expects it.
    const long long src_elems = (long long)BATCH * 2 * NN * NN;  // 16,777,216
    if ((long long)out_size > src_elems) {
        const long long tail = (long long)out_size - src_elems;
        cudaMemcpyAsync(out + src_elems, target,
                        (size_t)tail * sizeof(float),
                        cudaMemcpyDeviceToDevice);
    }
}